// round 5
// baseline (speedup 1.0000x reference)
#include <cuda_runtime.h>
#include <math.h>

#define BB 64
#define CC 80
#define DE 300
#define DE1 1024
#define JJ 4000
#define SS 100
#define KK 40
#define FDIM 2048

typedef unsigned long long ull;

// ---------------- scratch ----------------
__device__ __align__(16) float g_comb[144 * FDIM];    // rows 0-63: feat, 64-143: x
__device__ __align__(16) float g_b1t[CC * DE1];
__device__ __align__(16) float g_b2t[CC * DE1];
__device__ __align__(16) float g_Ahat[CC * CC];
__device__ __align__(16) float g_h[CC * DE1];
__device__ __align__(16) float g_ic[144 * JJ];        // rows 0-63: img, 64-143: cls
__device__ __align__(16) float g_pooled[BB * CC * KK];
__device__ __align__(16) float g_slabA[4 * CC * CC];
__device__ __align__(16) float g_slabT[2 * CC * DE1];
__device__ __align__(16) float g_slabY[2 * CC * FDIM];
__device__ __align__(16) float g_slabO[20 * BB * CC];

// ---------------- f32x2 helpers ----------------
__device__ __forceinline__ void unpack2(ull v, float& lo, float& hi) {
    asm("mov.b64 {%0,%1}, %2;" : "=f"(lo), "=f"(hi) : "l"(v));
}
__device__ __forceinline__ ull ffma2(ull a, ull b, ull c) {
    ull d; asm("fma.rn.f32x2 %0, %1, %2, %3;" : "=l"(d) : "l"(a), "l"(b), "l"(c)); return d;
}

// ---------------- small kernels ----------------

// MaxPool2d(14,14): one warp per (b, ch) -> g_comb rows 0-63
__global__ void k_maxpool(const float* __restrict__ f) {
    int warp = (blockIdx.x * blockDim.x + threadIdx.x) >> 5;
    int lane = threadIdx.x & 31;
    if (warp >= BB * FDIM) return;
    const float4* p = (const float4*)(f + (size_t)warp * 196);
    float m = -INFINITY;
    for (int i = lane; i < 49; i += 32) {
        float4 v = p[i];
        m = fmaxf(m, fmaxf(fmaxf(v.x, v.y), fmaxf(v.z, v.w)));
    }
    #pragma unroll
    for (int o = 16; o; o >>= 1) m = fmaxf(m, __shfl_xor_sync(0xffffffffu, m, o));
    if (lane == 0) g_comb[warp] = m;
}

// b1t[c][i] = sigmoid(Wb1[i,:] . X[:,c] + bb1[i]); X[d][c] = inp[d*80+c]
__global__ void k_b1b2(const float* __restrict__ Wb1, const float* __restrict__ bb1,
                       const float* __restrict__ Wb2, const float* __restrict__ bb2,
                       const float* __restrict__ inp) {
    int idx = blockIdx.x * blockDim.x + threadIdx.x;
    if (idx >= 2 * DE1 * CC) return;
    int which = idx / (DE1 * CC);
    int r = idx % (DE1 * CC);
    int i = r / CC, c = r % CC;
    const float* W = which ? Wb2 : Wb1;
    const float* bv = which ? bb2 : bb1;
    float s = bv[i];
    #pragma unroll 4
    for (int d = 0; d < DE; d++) s = fmaf(W[i * DE + d], inp[d * CC + c], s);
    s = 1.0f / (1.0f + expf(-s));
    (which ? g_b2t : g_b1t)[c * DE1 + i] = s;
}

// fused: Awave from slabA sum, dvec, Ahat, loss. one block 1024 thr.
__global__ void k_norm(float* __restrict__ out_loss) {
    __shared__ float Aw[CC * CC];
    __shared__ float dsh[CC];
    __shared__ float red[CC][9];
    __shared__ float lw[32];
    int t = threadIdx.x;
    for (int idx = t; idx < CC * CC; idx += 1024) {
        float s = g_slabA[idx] + g_slabA[CC * CC + idx]
                + g_slabA[2 * CC * CC + idx] + g_slabA[3 * CC * CC + idx];
        int i = idx / CC, j = idx - i * CC;
        Aw[idx] = s * (1.0f / CC) + (i == j ? 1.0f : 0.0f);
    }
    __syncthreads();
    if (t < CC * 8) {
        int i = t >> 3, p = t & 7;
        float s = 0.f;
        #pragma unroll
        for (int j = p * 10; j < p * 10 + 10; j++) s += Aw[i * CC + j];
        red[i][p] = s;
    }
    __syncthreads();
    if (t < CC) {
        float s = 0.f;
        #pragma unroll
        for (int p = 0; p < 8; p++) s += red[t][p];
        float d = rsqrtf(s);
        if (!isfinite(d)) d = 0.f;
        dsh[t] = d;
    }
    __syncthreads();
    float ls = 0.f;
    for (int idx = t; idx < CC * CC; idx += 1024) {
        int i = idx / CC, j = idx - i * CC;
        float v = dsh[i] * Aw[idx] * dsh[j];
        g_Ahat[idx] = v;
        ls += fabsf(v - (i == j ? 1.0f : 0.0f));
    }
    #pragma unroll
    for (int o = 16; o; o >>= 1) ls += __shfl_xor_sync(0xffffffffu, ls, o);
    if ((t & 31) == 0) lw[t >> 5] = ls;
    __syncthreads();
    if (t < 32) {
        float s = lw[t];
        #pragma unroll
        for (int o = 16; o; o >>= 1) s += __shfl_xor_sync(0xffffffffu, s, o);
        if (t == 0 && out_loss) *out_loss = s;
    }
}

// ---------------- dup-B FFMA2 GEMM ----------------
// C = A[M,K] @ op(B); TRANSB: B[N,K] (A@B^T), else B[K,N].
// BM=64, BN=64, BK=16, 256 threads, 4m x 4n per thread.
// B tile stored DUPLICATED in smem: dupcol(n) = 32*(n>>4) + 2*(n&15), two copies.
// -> compute: 1x ld.shared.v2.u64 (A pair) + 4x ld.shared.u64 (B dup) + 8 FFMA2 / kk.
// bsum: (non-trans only) B = sum of bsum planes of stride K*N (fused split-K reduce).
// TRANSB dual-B: blocks with m0 >= rowswitch use B1/bias1 (img|cls fusion).
// gridDim.z == 1: direct write to dst (+bias if TRANSB, leaky if set);
// else partial to slab[z] over k-range [z*kchunk, ...).
template <bool TRANSB>
__global__ void __launch_bounds__(256)
gemm_k(const float* __restrict__ A, const float* __restrict__ B0,
       const float* __restrict__ B1, const float* __restrict__ bias0,
       const float* __restrict__ bias1,
       float* __restrict__ dst, float* __restrict__ slab,
       int M, int N, int K, int kchunk, int bsum, int rowswitch, int leaky)
{
    __shared__ __align__(16) float As[2][16][68];
    __shared__ __align__(16) float Bs[2][16][132];
    const int tid = threadIdx.x;
    const int tx = tid & 15;         // n-lane
    const int ty = tid >> 4;         // m group (4 rows)
    const int m0 = blockIdx.y * 64, n0 = blockIdx.x * 64;
    const int kbeg = blockIdx.z * kchunk;
    const int kend = min(K, kbeg + kchunk);
    const int nsteps = (kend - kbeg + 15) >> 4;

    const float* Bsel = (TRANSB && B1 && m0 >= rowswitch) ? B1 : B0;
    const float* biassel = (TRANSB && bias1 && m0 >= rowswitch) ? bias1 : bias0;

    // loader thread mapping
    const int aq = tid & 3, aml = tid >> 2;          // A: k-quad, m-row
    const int bq = tid & 3, bnl = tid >> 2;          // B transb: k-quad, n-row
    const int bkk = tid >> 4, bn4 = (tid & 15) * 4;  // B non-trans: k-row, n-quad

    float4 ra, rb;

    auto ldg_step = [&](int k0) {
        // A
        {
            int gk = k0 + aq * 4;
            int gm = m0 + aml;
            ra = make_float4(0.f, 0.f, 0.f, 0.f);
            if (gm < M) {
                const float* ap = A + (size_t)gm * K + gk;
                if (gk + 3 < kend) ra = *(const float4*)ap;
                else {
                    if (gk + 0 < kend) ra.x = ap[0];
                    if (gk + 1 < kend) ra.y = ap[1];
                    if (gk + 2 < kend) ra.z = ap[2];
                }
            }
        }
        // B
        rb = make_float4(0.f, 0.f, 0.f, 0.f);
        if (TRANSB) {
            int gn = n0 + bnl;
            int gk = k0 + bq * 4;
            if (gn < N) {
                const float* bp = Bsel + (size_t)gn * K + gk;
                if (gk + 3 < kend) rb = *(const float4*)bp;
                else {
                    if (gk + 0 < kend) rb.x = bp[0];
                    if (gk + 1 < kend) rb.y = bp[1];
                    if (gk + 2 < kend) rb.z = bp[2];
                }
            }
        } else {
            int gk = k0 + bkk;
            int gn = n0 + bn4;
            if (gk < kend && gn < N) {
                const float* bp = B0 + (size_t)gk * N + gn;
                if (gn + 3 < N) {
                    rb = *(const float4*)bp;
                    for (int s = 1; s < bsum; s++) {
                        float4 t2 = *(const float4*)(bp + (size_t)s * K * N);
                        rb.x += t2.x; rb.y += t2.y; rb.z += t2.z; rb.w += t2.w;
                    }
                }
            }
        }
    };

    auto sts_step = [&](int bf) {
        As[bf][aq * 4 + 0][aml] = ra.x;
        As[bf][aq * 4 + 1][aml] = ra.y;
        As[bf][aq * 4 + 2][aml] = ra.z;
        As[bf][aq * 4 + 3][aml] = ra.w;
        if (TRANSB) {
            int dc = 32 * (bnl >> 4) + 2 * (bnl & 15);
            Bs[bf][bq * 4 + 0][dc] = rb.x; Bs[bf][bq * 4 + 0][dc + 1] = rb.x;
            Bs[bf][bq * 4 + 1][dc] = rb.y; Bs[bf][bq * 4 + 1][dc + 1] = rb.y;
            Bs[bf][bq * 4 + 2][dc] = rb.z; Bs[bf][bq * 4 + 2][dc + 1] = rb.z;
            Bs[bf][bq * 4 + 3][dc] = rb.w; Bs[bf][bq * 4 + 3][dc + 1] = rb.w;
        } else {
            #pragma unroll
            for (int j = 0; j < 4; j++) {
                int n = bn4 + j;
                int dc = 32 * (n >> 4) + 2 * (n & 15);
                float v = j == 0 ? rb.x : j == 1 ? rb.y : j == 2 ? rb.z : rb.w;
                Bs[bf][bkk][dc] = v;
                Bs[bf][bkk][dc + 1] = v;
            }
        }
    };

    ull acc0[4], acc1[4];
    #pragma unroll
    for (int i = 0; i < 4; i++) { acc0[i] = 0ull; acc1[i] = 0ull; }

    ldg_step(kbeg);
    sts_step(0);
    __syncthreads();

    int buf = 0;
    for (int s = 0; s < nsteps; s++) {
        bool more = (s + 1 < nsteps);
        if (more) ldg_step(kbeg + (s + 1) * 16);
        #pragma unroll
        for (int kk = 0; kk < 16; kk++) {
            ulonglong2 av = *(const ulonglong2*)&As[buf][kk][ty * 4];
            ull b0 = *(const ull*)&Bs[buf][kk][2 * tx];
            ull b1 = *(const ull*)&Bs[buf][kk][32 + 2 * tx];
            ull b2 = *(const ull*)&Bs[buf][kk][64 + 2 * tx];
            ull b3 = *(const ull*)&Bs[buf][kk][96 + 2 * tx];
            acc0[0] = ffma2(av.x, b0, acc0[0]); acc1[0] = ffma2(av.y, b0, acc1[0]);
            acc0[1] = ffma2(av.x, b1, acc0[1]); acc1[1] = ffma2(av.y, b1, acc1[1]);
            acc0[2] = ffma2(av.x, b2, acc0[2]); acc1[2] = ffma2(av.y, b2, acc1[2]);
            acc0[3] = ffma2(av.x, b3, acc0[3]); acc1[3] = ffma2(av.y, b3, acc1[3]);
        }
        if (more) {
            sts_step(buf ^ 1);
            __syncthreads();
            buf ^= 1;
        }
    }

    const bool direct = (gridDim.z == 1);
    float* op = direct ? dst : (slab + (size_t)blockIdx.z * M * N);
    int r0 = m0 + ty * 4;
    #pragma unroll
    for (int i = 0; i < 4; i++) {
        int gn = n0 + tx + 16 * i;
        if (gn >= N) continue;
        float v0, v1, v2, v3;
        unpack2(acc0[i], v0, v1);
        unpack2(acc1[i], v2, v3);
        float bv = (direct && TRANSB && biassel) ? biassel[gn] : 0.f;
        v0 += bv; v1 += bv; v2 += bv; v3 += bv;
        if (leaky && direct) {
            v0 = v0 > 0.f ? v0 : 0.2f * v0;
            v1 = v1 > 0.f ? v1 : 0.2f * v1;
            v2 = v2 > 0.f ? v2 : 0.2f * v2;
            v3 = v3 > 0.f ? v3 : 0.2f * v3;
        }
        if (r0 + 0 < M) op[(size_t)(r0 + 0) * N + gn] = v0;
        if (r0 + 1 < M) op[(size_t)(r0 + 1) * N + gn] = v1;
        if (r0 + 2 < M) op[(size_t)(r0 + 2) * N + gn] = v2;
        if (r0 + 3 < M) op[(size_t)(r0 + 3) * N + gn] = v3;
    }
}

// pooled[b][c][k] = sum_s img[b][k*100+s] * cls[c][k*100+s]; img/cls from g_ic
__global__ void k_pooled() {
    __shared__ float simg[32][101];
    __shared__ float scls[CC][101];
    int k = blockIdx.x % KK;
    int b0 = (blockIdx.x / KK) * 32;
    int tid = threadIdx.x;
    for (int idx = tid; idx < 32 * SS; idx += 256) {
        int r = idx / SS, s = idx % SS;
        simg[r][s] = g_ic[(size_t)(b0 + r) * JJ + k * SS + s];
    }
    for (int idx = tid; idx < CC * SS; idx += 256) {
        int c = idx / SS, s = idx % SS;
        scls[c][s] = g_ic[(size_t)(64 + c) * JJ + k * SS + s];
    }
    __syncthreads();
    for (int o = tid; o < 32 * CC; o += 256) {
        int lb = o / CC, c = o % CC;
        float acc = 0.f;
        #pragma unroll 4
        for (int s = 0; s < SS; s++) acc = fmaf(simg[lb][s], scls[c][s], acc);
        g_pooled[(size_t)(b0 + lb) * (CC * KK) + c * KK + k] = acc;
    }
}

// out = sum_z slabO[z] + bml
__global__ void k_rout(const float* __restrict__ bml, float* __restrict__ out) {
    int idx = blockIdx.x * blockDim.x + threadIdx.x;
    if (idx >= BB * CC) return;
    float s = 0.f;
    #pragma unroll 4
    for (int z = 0; z < 20; z++) s += g_slabO[z * BB * CC + idx];
    out[idx] = s + bml[idx % CC];
}

// ---------------- launcher ----------------

static inline float* symaddr(const void* sym) {
    void* p = nullptr;
    cudaGetSymbolAddress(&p, sym);
    return (float*)p;
}

extern "C" void kernel_launch(void* const* d_in, const int* in_sizes, int n_in,
                              void* d_out, int out_size) {
    const float* feature = (const float*)d_in[0];
    const float* inp     = (const float*)d_in[1];
    const float* Wb1     = (const float*)d_in[2];
    const float* bb1     = (const float*)d_in[3];
    const float* Wb2     = (const float*)d_in[4];
    const float* bb2     = (const float*)d_in[5];
    const float* Wg1     = (const float*)d_in[6];
    const float* Wg2     = (const float*)d_in[7];
    const float* Wimg    = (const float*)d_in[8];
    const float* bimg    = (const float*)d_in[9];
    const float* Wcls    = (const float*)d_in[10];
    const float* bcls    = (const float*)d_in[11];
    const float* Wml     = (const float*)d_in[12];
    const float* bml     = (const float*)d_in[13];
    float* out = (float*)d_out;

    float* p_comb  = symaddr(g_comb);
    float* p_b1t   = symaddr(g_b1t);
    float* p_b2t   = symaddr(g_b2t);
    float* p_Ahat  = symaddr(g_Ahat);
    float* p_h     = symaddr(g_h);
    float* p_ic    = symaddr(g_ic);
    float* p_pool  = symaddr(g_pooled);
    float* p_slabA = symaddr(g_slabA);
    float* p_slabT = symaddr(g_slabT);
    float* p_slabY = symaddr(g_slabY);
    float* p_slabO = symaddr(g_slabO);
    (void)p_pool;

    // 1) maxpool -> g_comb rows 0-63
    k_maxpool<<<(BB * FDIM * 32 + 255) / 256, 256>>>(feature);
    // 2) sigmoid branches -> b1t, b2t [80,1024]
    k_b1b2<<<(2 * DE1 * CC + 255) / 256, 256>>>(Wb1, bb1, Wb2, bb2, inp);
    // 3) Awave partials: b1t @ b2t^T  [80,80,K=1024], split 4
    gemm_k<true><<<dim3(2, 2, 4), 256>>>(p_b1t, p_b2t, nullptr, nullptr, nullptr,
                                         nullptr, p_slabA, CC, CC, DE1, 256, 1, 1 << 30, 0);
    // 4) fused norm (Awave sum, dvec, Ahat, loss)
    k_norm<<<1, 1024>>>(out_size > BB * CC ? out + BB * CC : nullptr);
    // 5) t1 partials: inp @ Wg1  [80,1024,K=300], split 2 -> slabT
    gemm_k<false><<<dim3(16, 2, 2), 256>>>(inp, Wg1, nullptr, nullptr, nullptr,
                                           nullptr, p_slabT, CC, DE1, DE, 160, 1, 1 << 30, 0);
    // 6) h = leaky(Ahat @ t1): B = slabT summed(2)  [80,1024,K=80]
    gemm_k<false><<<dim3(16, 2, 1), 256>>>(p_Ahat, p_slabT, nullptr, nullptr, nullptr,
                                           p_h, nullptr, CC, DE1, CC, CC, 2, 1 << 30, 1);
    // 7) y partials: h @ Wg2  [80,2048,K=1024], split 2 -> slabY
    gemm_k<false><<<dim3(32, 2, 2), 256>>>(p_h, Wg2, nullptr, nullptr, nullptr,
                                           nullptr, p_slabY, CC, FDIM, DE1, 512, 1, 1 << 30, 0);
    // 8) x = Ahat @ y: B = slabY summed(2) -> g_comb rows 64-143
    gemm_k<false><<<dim3(32, 2, 1), 256>>>(p_Ahat, p_slabY, nullptr, nullptr, nullptr,
                                           p_comb + 64 * FDIM, nullptr, CC, FDIM, CC, CC, 2, 1 << 30, 0);
    // 9) fused img|cls: [144,4000,K=2048], B/bias select at row 64, direct + bias
    gemm_k<true><<<dim3(63, 3, 1), 256>>>(p_comb, Wimg, Wcls, bimg, bcls,
                                          p_ic, nullptr, 144, JJ, FDIM, FDIM, 1, 64, 0);
    // 10) pooled einsum
    k_pooled<<<KK * 2, 256>>>();
    // 11) out partials: pooled @ Wml^T [64,80,K=3200], split 20
    gemm_k<true><<<dim3(2, 1, 20), 256>>>(p_pool, Wml, nullptr, nullptr, nullptr,
                                          nullptr, p_slabO, BB, CC, CC * KK, 160, 1, 1 << 30, 0);
    // 12) final reduce + bias
    k_rout<<<(BB * CC + 255) / 256, 256>>>(bml, out);
}